// round 1
// baseline (speedup 1.0000x reference)
#include <cuda_runtime.h>
#include <math.h>

#define L_SEQ 16384
#define H_DIM 128
#define P_DIM 256
#define NSEQ  512          // 256 channels x {re, im}
#define NCHUNK 128
#define CLEN   128         // NCHUNK * CLEN == L_SEQ

// Scratch (device globals; no allocations allowed)
__device__ float  g_buall[L_SEQ * NSEQ];   // (L, 512): Bu real | imag
__device__ float  g_x2all[L_SEQ * NSEQ];   // (L, 512): x2 real | imag
__device__ float2 g_final[NCHUNK * NSEQ];  // per-chunk local final states
__device__ float2 g_initv[NCHUNK * NSEQ];  // per-chunk initial states
__device__ float  g_W1[NSEQ * H_DIM];      // [Br; Bi]  (512, 128)
__device__ float  g_W2[H_DIM * NSEQ];      // [Cr, -Ci] (128, 512)

// ---------------------------------------------------------------------------
// Pack weights: W1 rows 0..255 = Br, 256..511 = Bi ; W2 cols 0..255 = Cr, 256..511 = -Ci
__global__ void prep_kernel(const float* __restrict__ B, const float* __restrict__ C) {
    int i = blockIdx.x * blockDim.x + threadIdx.x;
    if (i < P_DIM * H_DIM) {
        int p = i / H_DIM, h = i % H_DIM;
        g_W1[p * H_DIM + h]           = B[(p * H_DIM + h) * 2 + 0];
        g_W1[(P_DIM + p) * H_DIM + h] = B[(p * H_DIM + h) * 2 + 1];
    }
    if (i < H_DIM * P_DIM) {
        int h = i / P_DIM, p = i % P_DIM;
        g_W2[h * NSEQ + p]         =  C[(h * P_DIM + p) * 2 + 0];
        g_W2[h * NSEQ + P_DIM + p] = -C[(h * P_DIM + p) * 2 + 1];
    }
}

// ---------------------------------------------------------------------------
// Generic NT GEMM: out[m,n] = sum_k A[m,k] * W[n,k]  (A: MxK, W: NxK, both row-major)
// Block tile 64x64, BK=32, 256 threads, 4x4 per thread. EPI adds input*D residual.
template <bool EPI>
__global__ void gemm_nt(const float* __restrict__ A, const float* __restrict__ W,
                        float* __restrict__ out, int M, int N, int K,
                        const float* __restrict__ resid, const float* __restrict__ Dv) {
    const int BM = 64, BN = 64, BK = 32;
    __shared__ float As[BK][BM];
    __shared__ float Ws[BK][BN];
    int bm = blockIdx.y * BM, bn = blockIdx.x * BN;
    int tid = threadIdx.x;
    int ty = tid >> 4, tx = tid & 15;

    float acc[4][4] = {};

    for (int k0 = 0; k0 < K; k0 += BK) {
        // Load A tile (64x32) as float4, store transposed
        #pragma unroll
        for (int i = tid; i < (BM * BK) / 4; i += 256) {
            int r = i >> 3, c = (i & 7) << 2;
            float4 v = *reinterpret_cast<const float4*>(&A[(size_t)(bm + r) * K + k0 + c]);
            As[c][r] = v.x; As[c + 1][r] = v.y; As[c + 2][r] = v.z; As[c + 3][r] = v.w;
        }
        // Load W tile (64x32)
        #pragma unroll
        for (int i = tid; i < (BN * BK) / 4; i += 256) {
            int r = i >> 3, c = (i & 7) << 2;
            float4 v = *reinterpret_cast<const float4*>(&W[(size_t)(bn + r) * K + k0 + c]);
            Ws[c][r] = v.x; Ws[c + 1][r] = v.y; Ws[c + 2][r] = v.z; Ws[c + 3][r] = v.w;
        }
        __syncthreads();

        #pragma unroll
        for (int k = 0; k < BK; k++) {
            float a[4], b[4];
            #pragma unroll
            for (int i = 0; i < 4; i++) a[i] = As[k][ty * 4 + i];
            #pragma unroll
            for (int j = 0; j < 4; j++) b[j] = Ws[k][tx * 4 + j];
            #pragma unroll
            for (int i = 0; i < 4; i++)
                #pragma unroll
                for (int j = 0; j < 4; j++)
                    acc[i][j] = fmaf(a[i], b[j], acc[i][j]);
        }
        __syncthreads();
    }

    #pragma unroll
    for (int i = 0; i < 4; i++) {
        int m = bm + ty * 4 + i;
        int n = bn + tx * 4;
        float4 v = make_float4(acc[i][0], acc[i][1], acc[i][2], acc[i][3]);
        if (EPI) {
            float4 r = *reinterpret_cast<const float4*>(&resid[(size_t)m * N + n]);
            v.x += r.x * Dv[n + 0];
            v.y += r.y * Dv[n + 1];
            v.z += r.z * Dv[n + 2];
            v.w += r.w * Dv[n + 3];
        }
        *reinterpret_cast<float4*>(&out[(size_t)m * N + n]) = v;
    }
}

// ---------------------------------------------------------------------------
// Per-channel LinOSS-IM discretization constants
__device__ __forceinline__ void get_consts(const float* __restrict__ A_diag,
                                           const float* __restrict__ steps, int p,
                                           float& m11, float& m12, float& m21, float& m22,
                                           float& c1, float& c2) {
    float A  = fmaxf(A_diag[p], 0.0f);
    float dt = 1.0f / (1.0f + __expf(-steps[p]));
    float schur = 1.0f / (1.0f + dt * dt * A);
    m11 = 1.0f - dt * dt * A * schur;
    m12 = -dt * A * schur;
    m21 = dt * schur;
    m22 = schur;
    c1 = m11 * dt;   // f1 = c1 * Bu
    c2 = m21 * dt;   // f2 = c2 * Bu
}

// Pass A: local chunk scan with zero init, record final state per (chunk, seq)
__global__ void scan_passA(const float* __restrict__ A_diag, const float* __restrict__ steps) {
    int t = threadIdx.x;          // 0..511 : seq = comp*256 + p
    int c = blockIdx.x;           // chunk
    int p = t & (P_DIM - 1);
    float m11, m12, m21, m22, c1, c2;
    get_consts(A_diag, steps, p, m11, m12, m21, m22, c1, c2);

    float x1 = 0.0f, x2 = 0.0f;
    const float* bu = g_buall + (size_t)c * CLEN * NSEQ + t;
    #pragma unroll 8
    for (int s = 0; s < CLEN; s++) {
        float u = bu[s * NSEQ];
        float n1 = fmaf(m11, x1, fmaf(m12, x2, c1 * u));
        float n2 = fmaf(m21, x1, fmaf(m22, x2, c2 * u));
        x1 = n1; x2 = n2;
    }
    g_final[c * NSEQ + t] = make_float2(x1, x2);
}

// Pass B: sequential chunk-prefix per seq using Mpow = M^CLEN (7 squarings, CLEN=128)
__global__ void scan_passB(const float* __restrict__ A_diag, const float* __restrict__ steps) {
    int t = threadIdx.x;          // single block of 512
    int p = t & (P_DIM - 1);
    float m11, m12, m21, m22, c1, c2;
    get_consts(A_diag, steps, p, m11, m12, m21, m22, c1, c2);

    float a = m11, b = m12, c2x = m21, d = m22;
    #pragma unroll
    for (int i = 0; i < 7; i++) {  // M^(2^7) = M^128
        float na = a * a + b * c2x;
        float nb = a * b + b * d;
        float nc = c2x * a + d * c2x;
        float nd = c2x * b + d * d;
        a = na; b = nb; c2x = nc; d = nd;
    }

    float s1 = 0.0f, s2 = 0.0f;
    for (int c = 0; c < NCHUNK; c++) {
        g_initv[c * NSEQ + t] = make_float2(s1, s2);
        float2 f = g_final[c * NSEQ + t];
        float n1 = fmaf(a, s1, fmaf(b, s2, f.x));
        float n2 = fmaf(c2x, s1, fmaf(d, s2, f.y));
        s1 = n1; s2 = n2;
    }
}

// Pass C: re-run chunk scan with correct init, emit x2 stream
__global__ void scan_passC(const float* __restrict__ A_diag, const float* __restrict__ steps) {
    int t = threadIdx.x;
    int c = blockIdx.x;
    int p = t & (P_DIM - 1);
    float m11, m12, m21, m22, c1, c2;
    get_consts(A_diag, steps, p, m11, m12, m21, m22, c1, c2);

    float2 s0 = g_initv[c * NSEQ + t];
    float x1 = s0.x, x2 = s0.y;
    const float* bu = g_buall + (size_t)c * CLEN * NSEQ + t;
    float*       xo = g_x2all + (size_t)c * CLEN * NSEQ + t;
    #pragma unroll 8
    for (int s = 0; s < CLEN; s++) {
        float u = bu[s * NSEQ];
        float n1 = fmaf(m11, x1, fmaf(m12, x2, c1 * u));
        float n2 = fmaf(m21, x1, fmaf(m22, x2, c2 * u));
        x1 = n1; x2 = n2;
        xo[s * NSEQ] = x2;
    }
}

// ---------------------------------------------------------------------------
extern "C" void kernel_launch(void* const* d_in, const int* in_sizes, int n_in,
                              void* d_out, int out_size) {
    const float* input  = (const float*)d_in[0];  // (L, H)
    const float* A_diag = (const float*)d_in[1];  // (P,)
    const float* B      = (const float*)d_in[2];  // (P, H, 2)
    const float* C      = (const float*)d_in[3];  // (H, P, 2)
    const float* D      = (const float*)d_in[4];  // (H,)
    const float* steps  = (const float*)d_in[5];  // (P,)
    float* out = (float*)d_out;                   // (L, H)

    float *p_bu, *p_x2, *p_w1, *p_w2;
    cudaGetSymbolAddress((void**)&p_bu, g_buall);
    cudaGetSymbolAddress((void**)&p_x2, g_x2all);
    cudaGetSymbolAddress((void**)&p_w1, g_W1);
    cudaGetSymbolAddress((void**)&p_w2, g_W2);

    prep_kernel<<<128, 256>>>(B, C);

    // BuAll = input @ [Br;Bi]^T   (16384 x 512, K=128)
    gemm_nt<false><<<dim3(NSEQ / 64, L_SEQ / 64), 256>>>(
        input, p_w1, p_bu, L_SEQ, NSEQ, H_DIM, nullptr, nullptr);

    scan_passA<<<NCHUNK, NSEQ>>>(A_diag, steps);
    scan_passB<<<1, NSEQ>>>(A_diag, steps);
    scan_passC<<<NCHUNK, NSEQ>>>(A_diag, steps);

    // ys = x2all @ [Cr,-Ci]^T + input * D   (16384 x 128, K=512)
    gemm_nt<true><<<dim3(H_DIM / 64, L_SEQ / 64), 256>>>(
        p_x2, p_w2, out, L_SEQ, H_DIM, NSEQ, input, D);
}

// round 2
// speedup vs baseline: 1.8605x; 1.8605x over previous
#include <cuda_runtime.h>
#include <math.h>
#include <stdint.h>

#define L_SEQ 16384
#define H_DIM 128
#define P_DIM 256
#define NSEQ  512          // 256 channels x {re, im}
#define NCHUNK 128
#define CLEN   128         // NCHUNK * CLEN == L_SEQ

// Scratch (device globals; no allocations allowed)
__device__ float  g_buall[L_SEQ * NSEQ];   // (L, 512): Bu real | imag
__device__ float  g_x2all[L_SEQ * NSEQ];   // (L, 512): x2 real | imag
__device__ float2 g_final[NCHUNK * NSEQ];  // per-chunk local final states
__device__ float2 g_initv[NCHUNK * NSEQ];  // per-chunk initial states
__device__ float  g_W1[NSEQ * H_DIM];      // [Br; Bi]  (512, 128)
__device__ float  g_W2[H_DIM * NSEQ];      // [Cr, -Ci] (128, 512)

// ---------------------------------------------------------------------------
__global__ void prep_kernel(const float* __restrict__ B, const float* __restrict__ C) {
    int i = blockIdx.x * blockDim.x + threadIdx.x;
    if (i < P_DIM * H_DIM) {
        int p = i / H_DIM, h = i % H_DIM;
        g_W1[p * H_DIM + h]           = B[(p * H_DIM + h) * 2 + 0];
        g_W1[(P_DIM + p) * H_DIM + h] = B[(p * H_DIM + h) * 2 + 1];
    }
    if (i < H_DIM * P_DIM) {
        int h = i / P_DIM, p = i % P_DIM;
        g_W2[h * NSEQ + p]         =  C[(h * P_DIM + p) * 2 + 0];
        g_W2[h * NSEQ + P_DIM + p] = -C[(h * P_DIM + p) * 2 + 1];
    }
}

// ---------------------------------------------------------------------------
// tf32 helpers
__device__ __forceinline__ uint32_t f2tf32(float v) {
    uint32_t r;
    asm("cvt.rna.tf32.f32 %0, %1;" : "=r"(r) : "f"(v));
    return r;
}
__device__ __forceinline__ void mma_tf32(float* d, uint32_t a0, uint32_t a1,
                                         uint32_t a2, uint32_t a3,
                                         uint32_t b0, uint32_t b1) {
    asm volatile(
        "mma.sync.aligned.m16n8k8.row.col.f32.tf32.tf32.f32 "
        "{%0,%1,%2,%3},{%4,%5,%6,%7},{%8,%9},{%0,%1,%2,%3};\n"
        : "+f"(d[0]), "+f"(d[1]), "+f"(d[2]), "+f"(d[3])
        : "r"(a0), "r"(a1), "r"(a2), "r"(a3), "r"(b0), "r"(b1));
}

// XOR swizzle: element (row, k) of a [rows][32] tile at row*32 + (k ^ ((row&7)<<2))
#define SWZ(row, k) (((row) << 5) | ((k) ^ (((row) & 7) << 2)))

// ---------------------------------------------------------------------------
// 3xTF32 NT GEMM: out[m,n] = sum_k A[m,k] * W[n,k]; A: MxK row-major, W: NxK row-major.
// Block tile 128x64, BK=32, 256 threads (8 warps, 32x32 warp tiles).
template <bool EPI>
__global__ void __launch_bounds__(256)
gemm_tf32(const float* __restrict__ A, const float* __restrict__ W,
          float* __restrict__ out, int M, int N, int K,
          const float* __restrict__ resid, const float* __restrict__ Dv) {
    const int BM = 128, BN = 64, BK = 32;
    __shared__ float Ahi[BM * BK];  // swizzled
    __shared__ float Alo[BM * BK];
    __shared__ float Bhi[BN * BK];
    __shared__ float Blo[BN * BK];

    int tid  = threadIdx.x;
    int lane = tid & 31;
    int wid  = tid >> 5;
    int warp_m = (wid & 3) * 32;   // 4 warps along M
    int warp_n = (wid >> 2) * 32;  // 2 warps along N
    int gr = lane >> 2;            // 0..7
    int kq = lane & 3;             // 0..3

    int bm = blockIdx.y * BM, bn = blockIdx.x * BN;

    float acc[2][4][4];
    #pragma unroll
    for (int i = 0; i < 2; i++)
        #pragma unroll
        for (int j = 0; j < 4; j++)
            #pragma unroll
            for (int q = 0; q < 4; q++) acc[i][j][q] = 0.0f;

    for (int k0 = 0; k0 < K; k0 += BK) {
        // Load A tile 128x32 (1024 float4, 4 per thread)
        #pragma unroll
        for (int it = 0; it < 4; it++) {
            int idx = tid + it * 256;
            int r = idx >> 3, c4 = (idx & 7) << 2;
            float4 v = *reinterpret_cast<const float4*>(&A[(size_t)(bm + r) * K + k0 + c4]);
            int s = (r << 5) | (c4 ^ ((r & 7) << 2));
            float4 hi, lo;
            hi.x = __uint_as_float(f2tf32(v.x)); lo.x = v.x - hi.x;
            hi.y = __uint_as_float(f2tf32(v.y)); lo.y = v.y - hi.y;
            hi.z = __uint_as_float(f2tf32(v.z)); lo.z = v.z - hi.z;
            hi.w = __uint_as_float(f2tf32(v.w)); lo.w = v.w - hi.w;
            *reinterpret_cast<float4*>(&Ahi[s]) = hi;
            *reinterpret_cast<float4*>(&Alo[s]) = lo;
        }
        // Load B tile 64x32 (512 float4, 2 per thread)
        #pragma unroll
        for (int it = 0; it < 2; it++) {
            int idx = tid + it * 256;
            int r = idx >> 3, c4 = (idx & 7) << 2;
            float4 v = *reinterpret_cast<const float4*>(&W[(size_t)(bn + r) * K + k0 + c4]);
            int s = (r << 5) | (c4 ^ ((r & 7) << 2));
            float4 hi, lo;
            hi.x = __uint_as_float(f2tf32(v.x)); lo.x = v.x - hi.x;
            hi.y = __uint_as_float(f2tf32(v.y)); lo.y = v.y - hi.y;
            hi.z = __uint_as_float(f2tf32(v.z)); lo.z = v.z - hi.z;
            hi.w = __uint_as_float(f2tf32(v.w)); lo.w = v.w - hi.w;
            *reinterpret_cast<float4*>(&Bhi[s]) = hi;
            *reinterpret_cast<float4*>(&Blo[s]) = lo;
        }
        __syncthreads();

        #pragma unroll
        for (int kc = 0; kc < BK; kc += 8) {
            // A fragments (2 m-tiles) hi+lo
            uint32_t ah[2][4], al[2][4];
            #pragma unroll
            for (int mt = 0; mt < 2; mt++) {
                int r0 = warp_m + mt * 16 + gr;
                int r1 = r0 + 8;
                ah[mt][0] = __float_as_uint(Ahi[SWZ(r0, kc + kq)]);
                ah[mt][1] = __float_as_uint(Ahi[SWZ(r1, kc + kq)]);
                ah[mt][2] = __float_as_uint(Ahi[SWZ(r0, kc + 4 + kq)]);
                ah[mt][3] = __float_as_uint(Ahi[SWZ(r1, kc + 4 + kq)]);
                al[mt][0] = __float_as_uint(Alo[SWZ(r0, kc + kq)]);
                al[mt][1] = __float_as_uint(Alo[SWZ(r1, kc + kq)]);
                al[mt][2] = __float_as_uint(Alo[SWZ(r0, kc + 4 + kq)]);
                al[mt][3] = __float_as_uint(Alo[SWZ(r1, kc + 4 + kq)]);
            }
            // B fragments (4 n-tiles) hi+lo
            uint32_t bh[4][2], bl[4][2];
            #pragma unroll
            for (int nt = 0; nt < 4; nt++) {
                int c0 = warp_n + nt * 8 + gr;
                bh[nt][0] = __float_as_uint(Bhi[SWZ(c0, kc + kq)]);
                bh[nt][1] = __float_as_uint(Bhi[SWZ(c0, kc + 4 + kq)]);
                bl[nt][0] = __float_as_uint(Blo[SWZ(c0, kc + kq)]);
                bl[nt][1] = __float_as_uint(Blo[SWZ(c0, kc + 4 + kq)]);
            }
            #pragma unroll
            for (int mt = 0; mt < 2; mt++)
                #pragma unroll
                for (int nt = 0; nt < 4; nt++) {
                    float* d = acc[mt][nt];
                    mma_tf32(d, ah[mt][0], ah[mt][1], ah[mt][2], ah[mt][3],
                             bh[nt][0], bh[nt][1]);
                    mma_tf32(d, ah[mt][0], ah[mt][1], ah[mt][2], ah[mt][3],
                             bl[nt][0], bl[nt][1]);
                    mma_tf32(d, al[mt][0], al[mt][1], al[mt][2], al[mt][3],
                             bh[nt][0], bh[nt][1]);
                }
        }
        __syncthreads();
    }

    // Epilogue
    #pragma unroll
    for (int mt = 0; mt < 2; mt++) {
        #pragma unroll
        for (int nt = 0; nt < 4; nt++) {
            int row = bm + warp_m + mt * 16 + gr;
            int col = bn + warp_n + nt * 8 + 2 * kq;
            float2 v0 = make_float2(acc[mt][nt][0], acc[mt][nt][1]);
            float2 v1 = make_float2(acc[mt][nt][2], acc[mt][nt][3]);
            if (EPI) {
                float2 r0 = *reinterpret_cast<const float2*>(&resid[(size_t)row * N + col]);
                float2 r1 = *reinterpret_cast<const float2*>(&resid[(size_t)(row + 8) * N + col]);
                float d0 = Dv[col], d1 = Dv[col + 1];
                v0.x += r0.x * d0; v0.y += r0.y * d1;
                v1.x += r1.x * d0; v1.y += r1.y * d1;
            }
            *reinterpret_cast<float2*>(&out[(size_t)row * N + col]) = v0;
            *reinterpret_cast<float2*>(&out[(size_t)(row + 8) * N + col]) = v1;
        }
    }
}

// ---------------------------------------------------------------------------
__device__ __forceinline__ void get_consts(const float* __restrict__ A_diag,
                                           const float* __restrict__ steps, int p,
                                           float& m11, float& m12, float& m21, float& m22,
                                           float& c1, float& c2) {
    float A  = fmaxf(A_diag[p], 0.0f);
    float dt = 1.0f / (1.0f + __expf(-steps[p]));
    float schur = 1.0f / (1.0f + dt * dt * A);
    m11 = 1.0f - dt * dt * A * schur;
    m12 = -dt * A * schur;
    m21 = dt * schur;
    m22 = schur;
    c1 = m11 * dt;
    c2 = m21 * dt;
}

// Pass A: local chunk scan with zero init, record final state per (chunk, seq)
__global__ void scan_passA(const float* __restrict__ A_diag, const float* __restrict__ steps) {
    int t = threadIdx.x;
    int c = blockIdx.x;
    int p = t & (P_DIM - 1);
    float m11, m12, m21, m22, c1, c2;
    get_consts(A_diag, steps, p, m11, m12, m21, m22, c1, c2);

    float x1 = 0.0f, x2 = 0.0f;
    const float* bu = g_buall + (size_t)c * CLEN * NSEQ + t;
    #pragma unroll 8
    for (int s = 0; s < CLEN; s++) {
        float u = bu[s * NSEQ];
        float n1 = fmaf(m11, x1, fmaf(m12, x2, c1 * u));
        float n2 = fmaf(m21, x1, fmaf(m22, x2, c2 * u));
        x1 = n1; x2 = n2;
    }
    g_final[c * NSEQ + t] = make_float2(x1, x2);
}

// Pass B (parallel): per-seq Kogge-Stone scan over 128 chunk composites.
// 512 blocks (one per seq) x 128 threads (one per chunk).
__global__ void scan_passB_par(const float* __restrict__ A_diag,
                               const float* __restrict__ steps) {
    int seq = blockIdx.x;          // 0..511
    int c   = threadIdx.x;         // chunk 0..127
    int p   = seq & (P_DIM - 1);
    float m11, m12, m21, m22, c1u, c2u;
    get_consts(A_diag, steps, p, m11, m12, m21, m22, c1u, c2u);

    // A0 = M^CLEN via 7 squarings
    float a = m11, b = m12, cc = m21, d = m22;
    #pragma unroll
    for (int i = 0; i < 7; i++) {
        float na = a * a + b * cc;
        float nb = a * b + b * d;
        float nc = cc * a + d * cc;
        float nd = cc * b + d * d;
        a = na; b = nb; cc = nc; d = nd;
    }

    float2 f = g_final[c * NSEQ + seq];
    float ma = a, mb = b, mc = cc, md = d;
    float f1 = f.x, f2 = f.y;

    __shared__ float sa[NCHUNK], sb[NCHUNK], sc[NCHUNK], sd[NCHUNK];
    __shared__ float s1[NCHUNK], s2[NCHUNK];

    #pragma unroll
    for (int dstep = 1; dstep < NCHUNK; dstep <<= 1) {
        sa[c] = ma; sb[c] = mb; sc[c] = mc; sd[c] = md; s1[c] = f1; s2[c] = f2;
        __syncthreads();
        if (c >= dstep) {
            int j = c - dstep;
            float pa = sa[j], pb = sb[j], pc = sc[j], pd = sd[j];
            float p1 = s1[j], p2 = s2[j];
            float nf1 = ma * p1 + mb * p2 + f1;
            float nf2 = mc * p1 + md * p2 + f2;
            float na = ma * pa + mb * pc;
            float nb = ma * pb + mb * pd;
            float nc = mc * pa + md * pc;
            float nd = mc * pb + md * pd;
            ma = na; mb = nb; mc = nc; md = nd; f1 = nf1; f2 = nf2;
        }
        __syncthreads();
    }
    // inclusive[c] is (f1,f2); init for chunk c = inclusive[c-1]
    s1[c] = f1; s2[c] = f2;
    __syncthreads();
    float i1 = (c == 0) ? 0.0f : s1[c - 1];
    float i2 = (c == 0) ? 0.0f : s2[c - 1];
    g_initv[c * NSEQ + seq] = make_float2(i1, i2);
}

// Pass C: re-run chunk scan with correct init, emit x2 stream
__global__ void scan_passC(const float* __restrict__ A_diag, const float* __restrict__ steps) {
    int t = threadIdx.x;
    int c = blockIdx.x;
    int p = t & (P_DIM - 1);
    float m11, m12, m21, m22, c1, c2;
    get_consts(A_diag, steps, p, m11, m12, m21, m22, c1, c2);

    float2 s0 = g_initv[c * NSEQ + t];
    float x1 = s0.x, x2 = s0.y;
    const float* bu = g_buall + (size_t)c * CLEN * NSEQ + t;
    float*       xo = g_x2all + (size_t)c * CLEN * NSEQ + t;
    #pragma unroll 8
    for (int s = 0; s < CLEN; s++) {
        float u = bu[s * NSEQ];
        float n1 = fmaf(m11, x1, fmaf(m12, x2, c1 * u));
        float n2 = fmaf(m21, x1, fmaf(m22, x2, c2 * u));
        x1 = n1; x2 = n2;
        xo[s * NSEQ] = x2;
    }
}

// ---------------------------------------------------------------------------
extern "C" void kernel_launch(void* const* d_in, const int* in_sizes, int n_in,
                              void* d_out, int out_size) {
    const float* input  = (const float*)d_in[0];  // (L, H)
    const float* A_diag = (const float*)d_in[1];  // (P,)
    const float* B      = (const float*)d_in[2];  // (P, H, 2)
    const float* C      = (const float*)d_in[3];  // (H, P, 2)
    const float* D      = (const float*)d_in[4];  // (H,)
    const float* steps  = (const float*)d_in[5];  // (P,)
    float* out = (float*)d_out;                   // (L, H)

    float *p_bu, *p_x2, *p_w1, *p_w2;
    cudaGetSymbolAddress((void**)&p_bu, g_buall);
    cudaGetSymbolAddress((void**)&p_x2, g_x2all);
    cudaGetSymbolAddress((void**)&p_w1, g_W1);
    cudaGetSymbolAddress((void**)&p_w2, g_W2);

    prep_kernel<<<128, 256>>>(B, C);

    // BuAll = input @ [Br;Bi]^T   (16384 x 512, K=128)
    gemm_tf32<false><<<dim3(NSEQ / 64, L_SEQ / 128), 256>>>(
        input, p_w1, p_bu, L_SEQ, NSEQ, H_DIM, nullptr, nullptr);

    scan_passA<<<NCHUNK, NSEQ>>>(A_diag, steps);
    scan_passB_par<<<NSEQ, NCHUNK>>>(A_diag, steps);
    scan_passC<<<NCHUNK, NSEQ>>>(A_diag, steps);

    // ys = x2all @ [Cr,-Ci]^T + input * D   (16384 x 128, K=512)
    gemm_tf32<true><<<dim3(H_DIM / 64, L_SEQ / 128), 256>>>(
        p_x2, p_w2, out, L_SEQ, H_DIM, NSEQ, input, D);
}